// round 8
// baseline (speedup 1.0000x reference)
#include <cuda_runtime.h>
#include <math.h>

// Problem constants (fixed by the dataset)
#define BTOT 131072
#define INF  128
#define HH   256
#define KCH  32     // K chunk per smem stage
#define SMS  36     // smem row stride in floats: (r*36+c)%32 == (r*4+c)%32 -> conflict-free frags

// Scratch for p = relu(x@Wp^T + bp): 131072*256 fp32 = 134 MB (device global, no alloc)
static __device__ float g_P[(size_t)BTOT * (size_t)HH];

__device__ __forceinline__ unsigned f2tf(float x) {
    unsigned r;
    asm("cvt.rna.tf32.f32 %0, %1;" : "=r"(r) : "f"(x));
    return r;
}

// D += A(16x8,row) * B(8x8,col) in tf32 with fp32 accumulate
__device__ __forceinline__ void mma8(float d[4], const unsigned a[4], const unsigned b[2]) {
    asm volatile(
        "mma.sync.aligned.m16n8k8.row.col.f32.tf32.tf32.f32 "
        "{%0,%1,%2,%3}, {%4,%5,%6,%7}, {%8,%9}, {%0,%1,%2,%3};\n"
        : "+f"(d[0]), "+f"(d[1]), "+f"(d[2]), "+f"(d[3])
        : "r"(a[0]), "r"(a[1]), "r"(a[2]), "r"(a[3]), "r"(b[0]), "r"(b[1]));
}

// ---------------------------------------------------------------------------
// Kernel 1: P[B,256] = relu(X[B,128] @ Wp^T + bp)
// CTA: 256 thr (8 warps = 4m x 2n), tile M=128, N=64, K chunked by 32.
// ---------------------------------------------------------------------------
__global__ __launch_bounds__(256) void proj_kernel(
    const float* __restrict__ X,
    const float* __restrict__ Wp,
    const float* __restrict__ bp)
{
    __shared__ unsigned Xs[128 * SMS];
    __shared__ unsigned Ws[64 * SMS];

    const int tid  = threadIdx.x;
    const int lane = tid & 31;
    const int warp = tid >> 5;
    const int g    = lane >> 2;   // group id (row within 8)
    const int tg   = lane & 3;    // thread in group (k / col pair)
    const int wm   = warp >> 1;   // 0..3 -> 32 rows each
    const int wn   = warp & 1;    // 0..1 -> 32 cols each
    const int m0   = blockIdx.y * 128;
    const int n0   = blockIdx.x * 64;

    float acc[2][4][4];
    #pragma unroll
    for (int i = 0; i < 2; i++)
        #pragma unroll
        for (int j = 0; j < 4; j++)
            #pragma unroll
            for (int q = 0; q < 4; q++) acc[i][j][q] = 0.f;

    for (int kc = 0; kc < INF; kc += KCH) {
        // X chunk: 128 rows x 32 cols (1024 float4 slots / 256 thr = 4 each)
        #pragma unroll
        for (int i = 0; i < 4; i++) {
            int s   = tid + i * 256;
            int row = s >> 3;
            int c4  = (s & 7) << 2;
            float4 v = *(const float4*)&X[(size_t)(m0 + row) * INF + kc + c4];
            unsigned* p = &Xs[row * SMS + c4];
            p[0] = f2tf(v.x); p[1] = f2tf(v.y); p[2] = f2tf(v.z); p[3] = f2tf(v.w);
        }
        // Wp chunk: 64 rows x 32 cols (512 slots / 256 thr = 2 each)
        #pragma unroll
        for (int i = 0; i < 2; i++) {
            int s   = tid + i * 256;
            int row = s >> 3;
            int c4  = (s & 7) << 2;
            float4 v = *(const float4*)&Wp[(size_t)(n0 + row) * INF + kc + c4];
            unsigned* p = &Ws[row * SMS + c4];
            p[0] = f2tf(v.x); p[1] = f2tf(v.y); p[2] = f2tf(v.z); p[3] = f2tf(v.w);
        }
        __syncthreads();

        #pragma unroll
        for (int ks = 0; ks < KCH; ks += 8) {
            unsigned a[2][4];
            #pragma unroll
            for (int fm = 0; fm < 2; fm++) {
                int r = wm * 32 + fm * 16 + g;
                const unsigned* base = &Xs[r * SMS + ks + tg];
                a[fm][0] = base[0];
                a[fm][1] = base[8 * SMS];
                a[fm][2] = base[4];
                a[fm][3] = base[8 * SMS + 4];
            }
            #pragma unroll
            for (int fn = 0; fn < 4; fn++) {
                int nr = wn * 32 + fn * 8 + g;
                unsigned b[2];
                b[0] = Ws[nr * SMS + ks + tg];
                b[1] = Ws[nr * SMS + ks + tg + 4];
                #pragma unroll
                for (int fm = 0; fm < 2; fm++) mma8(acc[fm][fn], a[fm], b);
            }
        }
        __syncthreads();
    }

    // epilogue: +bias, relu, store to g_P
    #pragma unroll
    for (int fm = 0; fm < 2; fm++) {
        #pragma unroll
        for (int fn = 0; fn < 4; fn++) {
            int r0 = m0 + wm * 32 + fm * 16 + g;
            int c0 = n0 + wn * 32 + fn * 8 + tg * 2;
            float b0 = bp[c0], b1 = bp[c0 + 1];
            g_P[(size_t)r0 * HH + c0]           = fmaxf(acc[fm][fn][0] + b0, 0.f);
            g_P[(size_t)r0 * HH + c0 + 1]       = fmaxf(acc[fm][fn][1] + b1, 0.f);
            g_P[(size_t)(r0 + 8) * HH + c0]     = fmaxf(acc[fm][fn][2] + b0, 0.f);
            g_P[(size_t)(r0 + 8) * HH + c0 + 1] = fmaxf(acc[fm][fn][3] + b1, 0.f);
        }
    }
}

// ---------------------------------------------------------------------------
// Kernel 2: fused GRU cell.
// CTA: 256 thr (8 warps = 4m x 2n), tile M=128 rows, NJ=32 gate-columns.
// Accumulators per (row, j): a_r = i_r+h_r, a_z = i_z+h_z, i_n, h_n.
// Phase 0: A = h0, W = W_hh (-> a_r, a_z, h_n). Phase 1: A = P, W = W_ih (-> a_r, a_z, i_n).
// ---------------------------------------------------------------------------
__global__ __launch_bounds__(256) void gru_kernel(
    const float* __restrict__ H0,
    const float* __restrict__ Wih,
    const float* __restrict__ Whh,
    const float* __restrict__ bih,
    const float* __restrict__ bhh,
    float* __restrict__ out)
{
    __shared__ unsigned As[128 * SMS];
    __shared__ unsigned Ws[96 * SMS];   // rows: gate*32 + local_j

    const int tid  = threadIdx.x;
    const int lane = tid & 31;
    const int warp = tid >> 5;
    const int g    = lane >> 2;
    const int tg   = lane & 3;
    const int wm   = warp >> 1;   // 0..3 -> 32 rows each
    const int wn   = warp & 1;    // 0..1 -> 16 j each
    const int m0   = blockIdx.y * 128;
    const int j0   = blockIdx.x * 32;

    float ar[2][2][4], az[2][2][4], ain[2][2][4], ahn[2][2][4];
    #pragma unroll
    for (int i = 0; i < 2; i++)
        #pragma unroll
        for (int j = 0; j < 2; j++)
            #pragma unroll
            for (int q = 0; q < 4; q++) {
                ar[i][j][q] = 0.f; az[i][j][q] = 0.f;
                ain[i][j][q] = 0.f; ahn[i][j][q] = 0.f;
            }

    #pragma unroll
    for (int ph = 0; ph < 2; ph++) {
        const float* A = (ph == 0) ? H0 : (const float*)g_P;
        const float* W = (ph == 0) ? Whh : Wih;

        for (int kc = 0; kc < HH; kc += KCH) {
            // A chunk: 128 x 32 (1024 f4 slots / 256 thr = 4 each)
            #pragma unroll
            for (int i = 0; i < 4; i++) {
                int s   = tid + i * 256;
                int row = s >> 3;
                int c4  = (s & 7) << 2;
                float4 v = *(const float4*)&A[(size_t)(m0 + row) * HH + kc + c4];
                unsigned* p = &As[row * SMS + c4];
                p[0] = f2tf(v.x); p[1] = f2tf(v.y); p[2] = f2tf(v.z); p[3] = f2tf(v.w);
            }
            // W chunk: 96 x 32 (768 slots / 256 thr = 3 each); Ws row = gate*32 + jj
            #pragma unroll
            for (int i = 0; i < 3; i++) {
                int s    = tid + i * 256;
                int row  = s >> 3;
                int c4   = (s & 7) << 2;
                int gate = row >> 5;
                int jj   = row & 31;
                float4 v = *(const float4*)&W[(size_t)(gate * HH + j0 + jj) * HH + kc + c4];
                unsigned* p = &Ws[row * SMS + c4];
                p[0] = f2tf(v.x); p[1] = f2tf(v.y); p[2] = f2tf(v.z); p[3] = f2tf(v.w);
            }
            __syncthreads();

            #pragma unroll
            for (int ks = 0; ks < KCH; ks += 8) {
                unsigned a[2][4];
                #pragma unroll
                for (int fm = 0; fm < 2; fm++) {
                    int r = wm * 32 + fm * 16 + g;
                    const unsigned* base = &As[r * SMS + ks + tg];
                    a[fm][0] = base[0];
                    a[fm][1] = base[8 * SMS];
                    a[fm][2] = base[4];
                    a[fm][3] = base[8 * SMS + 4];
                }
                #pragma unroll
                for (int gate = 0; gate < 3; gate++) {
                    #pragma unroll
                    for (int fn = 0; fn < 2; fn++) {
                        int nr = gate * 32 + wn * 16 + fn * 8 + g;
                        unsigned b[2];
                        b[0] = Ws[nr * SMS + ks + tg];
                        b[1] = Ws[nr * SMS + ks + tg + 4];
                        #pragma unroll
                        for (int fm = 0; fm < 2; fm++) {
                            float* acc = (gate == 0) ? ar[fm][fn]
                                       : (gate == 1) ? az[fm][fn]
                                       : ((ph == 0) ? ahn[fm][fn] : ain[fm][fn]);
                            mma8(acc, a[fm], b);
                        }
                    }
                }
            }
            __syncthreads();
        }
    }

    // Epilogue: biases, gates, blend, write both output copies.
    const size_t BH = (size_t)BTOT * (size_t)HH;
    #pragma unroll
    for (int fm = 0; fm < 2; fm++) {
        #pragma unroll
        for (int fn = 0; fn < 2; fn++) {
            int rbase = m0 + wm * 32 + fm * 16 + g;
            int jb    = j0 + wn * 16 + fn * 8 + tg * 2;
            #pragma unroll
            for (int q = 0; q < 4; q++) {
                int row = rbase + (q >> 1) * 8;
                int j   = jb + (q & 1);
                float vr  = ar[fm][fn][q]  + bih[j]          + bhh[j];
                float vz  = az[fm][fn][q]  + bih[HH + j]     + bhh[HH + j];
                float vin = ain[fm][fn][q] + bih[2 * HH + j];
                float vhn = ahn[fm][fn][q] + bhh[2 * HH + j];
                float r = 1.f / (1.f + __expf(-vr));
                float z = 1.f / (1.f + __expf(-vz));
                float n = tanhf(vin + r * vhn);
                float h0v = H0[(size_t)row * HH + j];
                float nh  = fmaf(z, h0v - n, n);   // (1-z)*n + z*h0
                size_t idx = (size_t)row * HH + j;
                out[idx]      = nh;
                out[BH + idx] = nh;
            }
        }
    }
}

// ---------------------------------------------------------------------------
// kernel_launch: inputs in metadata order x, h, Wp, bp, W_ih, W_hh, b_ih, b_hh
// ---------------------------------------------------------------------------
extern "C" void kernel_launch(void* const* d_in, const int* in_sizes, int n_in,
                              void* d_out, int out_size) {
    const float* x   = (const float*)d_in[0];
    const float* h   = (const float*)d_in[1];   // (1, B, H) contiguous == (B, H)
    const float* Wp  = (const float*)d_in[2];
    const float* bp  = (const float*)d_in[3];
    const float* Wih = (const float*)d_in[4];
    const float* Whh = (const float*)d_in[5];
    const float* bih = (const float*)d_in[6];
    const float* bhh = (const float*)d_in[7];
    float* out = (float*)d_out;

    dim3 gA(HH / 64, BTOT / 128);   // (4, 1024)
    proj_kernel<<<gA, 256>>>(x, Wp, bp);

    dim3 gB(HH / 32, BTOT / 128);   // (8, 1024) — j fastest for L2 reuse of h/P tiles
    gru_kernel<<<gB, 256>>>(h, Wih, Whh, bih, bhh, out);
}